// round 15
// baseline (speedup 1.0000x reference)
#include <cuda_runtime.h>
#include <cuda_bf16.h>
#include <cstdint>

#define BATCH 4
#define CIN   128
#define COUT  256
#define HW    1024
#define TILE_O 32
#define TILE_P 64
#define THREADS 128
#define KC     32            // k-chunk
#define NCHUNK (CIN / KC)    // 4

// smem (bytes): strides are 16B multiples with (stride/4 mod 32)==4 -> ldmatrix
// row addresses walk 4 banks per row, conflict-free per 8-row phase.
#define A_STRIDE 272         // 128 halves + 8 pad
#define B_STRIDE 144         // 64 halves + 8 pad
#define SMEM_A   0                                  // [32 o][128 k] bf16
#define SMEM_B0  (TILE_O * A_STRIDE)                // 8704
#define SMEM_B1  (SMEM_B0 + KC * B_STRIDE)          // 13312
#define SMEM_TOTAL (SMEM_B1 + KC * B_STRIDE)        // 17920 (<48KB)

#define ABS2 0x7FFF7FFFu     // clears both bf16 sign bits

__device__ __forceinline__ uint32_t smem_u32(const void* p) {
    uint32_t a;
    asm("{ .reg .u64 t; cvta.to.shared.u64 t, %1; cvt.u32.u64 %0, t; }" : "=r"(a) : "l"(p));
    return a;
}
__device__ __forceinline__ uint32_t pack_bf16x2(float lo, float hi) {
    uint32_t r;
    asm("cvt.rn.bf16x2.f32 %0, %1, %2;" : "=r"(r) : "f"(hi), "f"(lo));
    return r;
}
__device__ __forceinline__ void sts64(uint32_t addr, uint32_t a, uint32_t b) {
    asm volatile("st.shared.v2.b32 [%0], {%1,%2};" :: "r"(addr), "r"(a), "r"(b) : "memory");
}
__device__ __forceinline__ void ldsm_x4(uint32_t addr, uint32_t* r) {
    asm volatile("ldmatrix.sync.aligned.m8n8.x4.shared.b16 {%0,%1,%2,%3}, [%4];"
                 : "=r"(r[0]), "=r"(r[1]), "=r"(r[2]), "=r"(r[3]) : "r"(addr));
}
__device__ __forceinline__ void ldsm_x4_trans(uint32_t addr, uint32_t* r) {
    asm volatile("ldmatrix.sync.aligned.m8n8.x4.trans.shared.b16 {%0,%1,%2,%3}, [%4];"
                 : "=r"(r[0]), "=r"(r[1]), "=r"(r[2]), "=r"(r[3]) : "r"(addr));
}
__device__ __forceinline__ void mma_16816(float* c, const uint32_t* a, const uint32_t* b) {
    asm volatile(
        "mma.sync.aligned.m16n8k16.row.col.f32.bf16.bf16.f32 "
        "{%0,%1,%2,%3}, {%4,%5,%6,%7}, {%8,%9}, {%0,%1,%2,%3};"
        : "+f"(c[0]), "+f"(c[1]), "+f"(c[2]), "+f"(c[3])
        : "r"(a[0]), "r"(a[1]), "r"(a[2]), "r"(a[3]), "r"(b[0]), "r"(b[1]));
}

// One k16 step of the abs-trick mainloop: accS += W·X, accA += |W|·|X|.
__device__ __forceinline__ void k_step(uint32_t aAddr, uint32_t bAddr,
                                       float accS[4][4], float accA[4][4]) {
    uint32_t aw[4], bx[2][4];
    ldsm_x4(aAddr, aw);
    ldsm_x4_trans(bAddr, bx[0]);
    ldsm_x4_trans(bAddr + 32, bx[1]);
    uint32_t wa[4], xa[2][4];
#pragma unroll
    for (int j = 0; j < 4; j++) wa[j] = aw[j] & ABS2;
#pragma unroll
    for (int g = 0; g < 2; g++)
#pragma unroll
        for (int j = 0; j < 4; j++) xa[g][j] = bx[g][j] & ABS2;
    mma_16816(accS[0], aw, &bx[0][0]);
    mma_16816(accA[0], wa, &xa[0][0]);
    mma_16816(accS[1], aw, &bx[0][2]);
    mma_16816(accA[1], wa, &xa[0][2]);
    mma_16816(accS[2], aw, &bx[1][0]);
    mma_16816(accA[2], wa, &xa[1][0]);
    mma_16816(accS[3], aw, &bx[1][2]);
    mma_16816(accA[3], wa, &xa[1][2]);
}

__global__ __launch_bounds__(THREADS, 4)
void pw_relu_mma_kernel(const float* __restrict__ x,
                        const float* __restrict__ w,
                        float* __restrict__ out) {
    extern __shared__ char smem[];
    const uint32_t sb = smem_u32(smem);
    const int tid  = threadIdx.x;
    const int lane = tid & 31;
    const int wid  = tid >> 5;
    const int b  = blockIdx.z;
    const int o0 = blockIdx.y * TILE_O;
    const int p0 = blockIdx.x * TILE_P;

    // ---- per-chunk staging maps ----
    // W: thread covers (o = tid>>2, k-f4 = tid&3 and +4) within each chunk
    const int ow = tid >> 2;               // 0..31
    const int kf = tid & 3;                // 0..3
    const float* wrow = w + (size_t)(o0 + ow) * CIN + kf * 4;
    const uint32_t aStsBase = sb + SMEM_A + (uint32_t)ow * A_STRIDE + kf * 8;
    // X: thread covers (rows rl+8it, it<4, p = 4*pf) within each chunk
    const int pf = tid & 15;
    const int rl = tid >> 4;               // 0..7
    const float* xb = x + (size_t)b * CIN * HW + p0 + pf * 4;

    // ---- prologue: chunk 0 only (6 f4 on the critical path) ----
    float4 wva = *(const float4*)(wrow);
    float4 wvb = *(const float4*)(wrow + 16);
    float4 xv[4];
#pragma unroll
    for (int it = 0; it < 4; it++)
        xv[it] = *(const float4*)(xb + (size_t)(rl + it * 8) * HW);

    sts64(aStsBase,      pack_bf16x2(wva.x, wva.y), pack_bf16x2(wva.z, wva.w));
    sts64(aStsBase + 32, pack_bf16x2(wvb.x, wvb.y), pack_bf16x2(wvb.z, wvb.w));
#pragma unroll
    for (int it = 0; it < 4; it++) {
        float4 v = xv[it];
        sts64(sb + SMEM_B0 + (uint32_t)(rl + it * 8) * B_STRIDE + pf * 8,
              pack_bf16x2(v.x, v.y), pack_bf16x2(v.z, v.w));
    }
    __syncthreads();

    // ---- per-warp fragment bases ----
    const int warp_m = wid & 1;
    const int warp_n = wid >> 1;
    const uint32_t aAddr0 = sb + SMEM_A + (uint32_t)(warp_m * 16 + (lane & 15)) * A_STRIDE
                            + (uint32_t)(lane >> 4) * 16;
    const uint32_t bFrag  = (uint32_t)(lane & 15) * B_STRIDE
                            + (uint32_t)(warp_n * 64) + (uint32_t)(lane >> 4) * 16;
    const uint32_t bBuf[2] = { sb + SMEM_B0 + bFrag, sb + SMEM_B1 + bFrag };

    float accS[4][4], accA[4][4];
#pragma unroll
    for (int ns = 0; ns < 4; ns++)
#pragma unroll
        for (int j = 0; j < 4; j++) { accS[ns][j] = 0.f; accA[ns][j] = 0.f; }

    // ---- pipelined chunks: LDG(c+1) -> compute(c) -> STS(c+1) -> sync ----
#pragma unroll
    for (int c = 0; c < NCHUNK; c++) {
        float4 nw0, nw1, nx[4];
        if (c + 1 < NCHUNK) {
            nw0 = *(const float4*)(wrow + (c + 1) * KC);
            nw1 = *(const float4*)(wrow + (c + 1) * KC + 16);
#pragma unroll
            for (int it = 0; it < 4; it++)
                nx[it] = *(const float4*)(xb + (size_t)((c + 1) * KC + rl + it * 8) * HW);
        }

        k_step(aAddr0 + (uint32_t)(2 * c) * 32,     bBuf[c & 1],                      accS, accA);
        k_step(aAddr0 + (uint32_t)(2 * c + 1) * 32, bBuf[c & 1] + 16 * B_STRIDE,      accS, accA);

        if (c + 1 < NCHUNK) {
            const uint32_t aDst = aStsBase + (uint32_t)(c + 1) * 64;
            sts64(aDst,      pack_bf16x2(nw0.x, nw0.y), pack_bf16x2(nw0.z, nw0.w));
            sts64(aDst + 32, pack_bf16x2(nw1.x, nw1.y), pack_bf16x2(nw1.z, nw1.w));
            const uint32_t bDst = sb + ((c & 1) ? SMEM_B0 : SMEM_B1);
#pragma unroll
            for (int it = 0; it < 4; it++) {
                float4 v = nx[it];
                sts64(bDst + (uint32_t)(rl + it * 8) * B_STRIDE + pf * 8,
                      pack_bf16x2(v.x, v.y), pack_bf16x2(v.z, v.w));
            }
            __syncthreads();
        }
    }

    // ---- epilogue: out = 0.5*(S + A), coalesced float2 stores ----
    const int r  = lane >> 2;
    const int c2 = (lane & 3) * 2;
    float* ob = out + ((size_t)b * COUT + o0 + warp_m * 16) * HW + p0 + warp_n * 32 + c2;
#pragma unroll
    for (int ns = 0; ns < 4; ns++) {
        float v0 = (accS[ns][0] + accA[ns][0]) * 0.5f;
        float v1 = (accS[ns][1] + accA[ns][1]) * 0.5f;
        float v2 = (accS[ns][2] + accA[ns][2]) * 0.5f;
        float v3 = (accS[ns][3] + accA[ns][3]) * 0.5f;
        *(float2*)(ob + (size_t)r * HW + ns * 8)       = make_float2(v0, v1);
        *(float2*)(ob + (size_t)(r + 8) * HW + ns * 8) = make_float2(v2, v3);
    }
}

extern "C" void kernel_launch(void* const* d_in, const int* in_sizes, int n_in,
                              void* d_out, int out_size) {
    const float* x = (const float*)d_in[0];   // (4,128,32,32)
    const float* w = (const float*)d_in[1];   // (256*128,1,1,1)
    float* out = (float*)d_out;               // (4,256,32,32)
    dim3 grid(HW / TILE_P, COUT / TILE_O, BATCH);   // (16, 8, 4) = 512 CTAs
    pw_relu_mma_kernel<<<grid, THREADS, SMEM_TOTAL>>>(x, w, out);
}

// round 17
// speedup vs baseline: 1.0072x; 1.0072x over previous
#include <cuda_runtime.h>
#include <cuda_bf16.h>
#include <cstdint>

#define BATCH 4
#define CIN   128
#define COUT  256
#define HW    1024
#define TILE_O 32
#define TILE_P 64
#define THREADS 256
#define KC     64            // k-chunk (2 chunks)

// smem (bytes): strides are 16B multiples with (stride/4 mod 32)==4 -> ldmatrix
// row addresses walk 4 banks per row, conflict-free per 8-row phase.
#define A_STRIDE 272         // 128 halves + 8 pad
#define B_STRIDE 144         // 64 halves + 8 pad
#define SMEM_A   0                                  // [32 o][128 k] bf16
#define SMEM_B0  (TILE_O * A_STRIDE)                // 8704
#define SMEM_B1  (SMEM_B0 + KC * B_STRIDE)          // 17920
#define SMEM_TOTAL (SMEM_B1 + KC * B_STRIDE)        // 27136 (<48KB)

#define ABS2 0x7FFF7FFFu     // clears both bf16 sign bits

__device__ __forceinline__ uint32_t smem_u32(const void* p) {
    uint32_t a;
    asm("{ .reg .u64 t; cvta.to.shared.u64 t, %1; cvt.u32.u64 %0, t; }" : "=r"(a) : "l"(p));
    return a;
}
__device__ __forceinline__ uint32_t pack_bf16x2(float lo, float hi) {
    uint32_t r;
    asm("cvt.rn.bf16x2.f32 %0, %1, %2;" : "=r"(r) : "f"(hi), "f"(lo));
    return r;
}
__device__ __forceinline__ void sts64(uint32_t addr, uint32_t a, uint32_t b) {
    asm volatile("st.shared.v2.b32 [%0], {%1,%2};" :: "r"(addr), "r"(a), "r"(b) : "memory");
}
__device__ __forceinline__ void ldsm_x4(uint32_t addr, uint32_t* r) {
    asm volatile("ldmatrix.sync.aligned.m8n8.x4.shared.b16 {%0,%1,%2,%3}, [%4];"
                 : "=r"(r[0]), "=r"(r[1]), "=r"(r[2]), "=r"(r[3]) : "r"(addr));
}
__device__ __forceinline__ void ldsm_x4_trans(uint32_t addr, uint32_t* r) {
    asm volatile("ldmatrix.sync.aligned.m8n8.x4.trans.shared.b16 {%0,%1,%2,%3}, [%4];"
                 : "=r"(r[0]), "=r"(r[1]), "=r"(r[2]), "=r"(r[3]) : "r"(addr));
}
__device__ __forceinline__ void mma_16816(float* c, const uint32_t* a, const uint32_t* b) {
    asm volatile(
        "mma.sync.aligned.m16n8k16.row.col.f32.bf16.bf16.f32 "
        "{%0,%1,%2,%3}, {%4,%5,%6,%7}, {%8,%9}, {%0,%1,%2,%3};"
        : "+f"(c[0]), "+f"(c[1]), "+f"(c[2]), "+f"(c[3])
        : "r"(a[0]), "r"(a[1]), "r"(a[2]), "r"(a[3]), "r"(b[0]), "r"(b[1]));
}

// One k16 step, 16(o) x 16(p) warp tile: accS += W·X, accA += |W|·|X|.
__device__ __forceinline__ void k_step(uint32_t aAddr, uint32_t bAddr,
                                       float accS[2][4], float accA[2][4]) {
    uint32_t aw[4], bx[4];
    ldsm_x4(aAddr, aw);
    ldsm_x4_trans(bAddr, bx);
    uint32_t wa[4], xa[4];
#pragma unroll
    for (int j = 0; j < 4; j++) { wa[j] = aw[j] & ABS2; xa[j] = bx[j] & ABS2; }
    mma_16816(accS[0], aw, &bx[0]);
    mma_16816(accA[0], wa, &xa[0]);
    mma_16816(accS[1], aw, &bx[2]);
    mma_16816(accA[1], wa, &xa[2]);
}

__global__ __launch_bounds__(THREADS, 3)
void pw_relu_mma_kernel(const float* __restrict__ x,
                        const float* __restrict__ w,
                        float* __restrict__ out) {
    extern __shared__ char smem[];
    const uint32_t sb = smem_u32(smem);
    const int tid  = threadIdx.x;
    const int lane = tid & 31;
    const int wid  = tid >> 5;             // 0..7
    const int b  = blockIdx.z;
    const int o0 = blockIdx.y * TILE_O;
    const int p0 = blockIdx.x * TILE_P;

    // ---- staging maps (per 64-row chunk) ----
    // X: thread covers rows rl+16it (it<4), col p=4*pf
    const int pf = tid & 15;
    const int rl = tid >> 4;               // 0..15
    const float* xb = x + (size_t)b * CIN * HW + p0 + pf * 4;
    // W: thread covers row ow, f4 indices kf and kf+8 within the 64-k chunk
    const int ow = tid >> 3;               // 0..31
    const int kf = tid & 7;                // 0..7
    const float* wrow = w + (size_t)(o0 + ow) * CIN;
    const uint32_t aStsBase = sb + SMEM_A + (uint32_t)ow * A_STRIDE;

    // ---- prologue: chunk 0 (W 2 f4 + X 4 f4 on the critical path) ----
    float4 wv0 = *(const float4*)(wrow + kf * 4);
    float4 wv1 = *(const float4*)(wrow + kf * 4 + 32);
    float4 xv[4];
#pragma unroll
    for (int it = 0; it < 4; it++)
        xv[it] = *(const float4*)(xb + (size_t)(rl + it * 16) * HW);

    sts64(aStsBase + kf * 8,      pack_bf16x2(wv0.x, wv0.y), pack_bf16x2(wv0.z, wv0.w));
    sts64(aStsBase + kf * 8 + 64, pack_bf16x2(wv1.x, wv1.y), pack_bf16x2(wv1.z, wv1.w));
#pragma unroll
    for (int it = 0; it < 4; it++) {
        float4 v = xv[it];
        sts64(sb + SMEM_B0 + (uint32_t)(rl + it * 16) * B_STRIDE + pf * 8,
              pack_bf16x2(v.x, v.y), pack_bf16x2(v.z, v.w));
    }
    __syncthreads();

    // ---- issue chunk 1 LDGs now: latency rides under chunk-0 compute ----
    float4 yw0 = *(const float4*)(wrow + 64 + kf * 4);
    float4 yw1 = *(const float4*)(wrow + 64 + kf * 4 + 32);
    float4 yv[4];
#pragma unroll
    for (int it = 0; it < 4; it++)
        yv[it] = *(const float4*)(xb + (size_t)(64 + rl + it * 16) * HW);

    // ---- per-warp fragment bases: warp grid 2(m) x 4(n), tile 16x16 ----
    const int warp_m = wid & 1;
    const int warp_n = wid >> 1;           // 0..3
    const uint32_t aAddr0 = sb + SMEM_A + (uint32_t)(warp_m * 16 + (lane & 15)) * A_STRIDE
                            + (uint32_t)(lane >> 4) * 16;
    const uint32_t bFrag  = (uint32_t)(lane & 15) * B_STRIDE
                            + (uint32_t)(warp_n * 32) + (uint32_t)(lane >> 4) * 16;

    float accS[2][4], accA[2][4];
#pragma unroll
    for (int ns = 0; ns < 2; ns++)
#pragma unroll
        for (int j = 0; j < 4; j++) { accS[ns][j] = 0.f; accA[ns][j] = 0.f; }

    // ---- chunk 0 compute ----
#pragma unroll
    for (int kk = 0; kk < 4; kk++)
        k_step(aAddr0 + (uint32_t)kk * 32,
               sb + SMEM_B0 + bFrag + (uint32_t)kk * (16 * B_STRIDE), accS, accA);

    // ---- stage chunk 1 ----
    sts64(aStsBase + 128 + kf * 8,      pack_bf16x2(yw0.x, yw0.y), pack_bf16x2(yw0.z, yw0.w));
    sts64(aStsBase + 128 + kf * 8 + 64, pack_bf16x2(yw1.x, yw1.y), pack_bf16x2(yw1.z, yw1.w));
#pragma unroll
    for (int it = 0; it < 4; it++) {
        float4 v = yv[it];
        sts64(sb + SMEM_B1 + (uint32_t)(rl + it * 16) * B_STRIDE + pf * 8,
              pack_bf16x2(v.x, v.y), pack_bf16x2(v.z, v.w));
    }
    __syncthreads();

    // ---- chunk 1 compute ----
#pragma unroll
    for (int kk = 0; kk < 4; kk++)
        k_step(aAddr0 + (uint32_t)(4 + kk) * 32,
               sb + SMEM_B1 + bFrag + (uint32_t)kk * (16 * B_STRIDE), accS, accA);

    // ---- epilogue: out = 0.5*(S + A), coalesced float2 stores ----
    const int r  = lane >> 2;
    const int c2 = (lane & 3) * 2;
    float* ob = out + ((size_t)b * COUT + o0 + warp_m * 16) * HW + p0 + warp_n * 16 + c2;
#pragma unroll
    for (int ns = 0; ns < 2; ns++) {
        float v0 = (accS[ns][0] + accA[ns][0]) * 0.5f;
        float v1 = (accS[ns][1] + accA[ns][1]) * 0.5f;
        float v2 = (accS[ns][2] + accA[ns][2]) * 0.5f;
        float v3 = (accS[ns][3] + accA[ns][3]) * 0.5f;
        *(float2*)(ob + (size_t)r * HW + ns * 8)       = make_float2(v0, v1);
        *(float2*)(ob + (size_t)(r + 8) * HW + ns * 8) = make_float2(v2, v3);
    }
}

extern "C" void kernel_launch(void* const* d_in, const int* in_sizes, int n_in,
                              void* d_out, int out_size) {
    const float* x = (const float*)d_in[0];   // (4,128,32,32)
    const float* w = (const float*)d_in[1];   // (256*128,1,1,1)
    float* out = (float*)d_out;               // (4,256,32,32)
    dim3 grid(HW / TILE_P, COUT / TILE_O, BATCH);   // (16, 8, 4) = 512 CTAs
    pw_relu_mma_kernel<<<grid, THREADS, SMEM_TOTAL>>>(x, w, out);
}